// round 16
// baseline (speedup 1.0000x reference)
#include <cuda_runtime.h>
#include <cuda_bf16.h>
#include <cuda_fp16.h>
#include <math_constants.h>
#include <cstdint>

#define D 128
#define MAXN 50000
#define MAXE 800000

// -------- scratch (device globals: allocation-free contract) --------
__device__ __half g_z16[MAXN * D];    // projected features (fp16, gather path)
__device__ float g_h[MAXN * D];       // layer output -> next layer input
__device__ float g_el[MAXN];
__device__ float g_er[MAXN];
__device__ float g_e[MAXE];           // per-edge scratch (fallback path only)
__device__ int   g_cnt[MAXN];
__device__ int   g_off[MAXN + 1];
__device__ int   g_woff[MAXN];
__device__ int   g_csr_src[MAXE];
__device__ __nv_bfloat16 g_wh[3][D * D];   // W^T hi split, [n][k] K-major
__device__ __nv_bfloat16 g_wl[3][D * D];   // W^T lo split

// ================= CSR build ================================================

__global__ void k_hist(const int* __restrict__ dst, int eN) {
    int i = blockIdx.x * blockDim.x + threadIdx.x;
    if (i < eN) atomicAdd(&g_cnt[dst[i]], 1);
}
__global__ __launch_bounds__(1024) void k_scan(int n, int eN) {
    __shared__ int part[1024];
    int t = threadIdx.x;
    int chunk = (n + 1023) / 1024;
    int lo = t * chunk;
    int hi = lo + chunk; if (hi > n) hi = n; if (lo > n) lo = n;
    int s = 0;
    for (int i = lo; i < hi; i++) s += g_cnt[i];
    part[t] = s;
    __syncthreads();
    for (int off = 1; off < 1024; off <<= 1) {
        int v = (t >= off) ? part[t - off] : 0;
        __syncthreads();
        part[t] += v;
        __syncthreads();
    }
    int run = (t == 0) ? 0 : part[t - 1];
    for (int i = lo; i < hi; i++) {
        g_off[i] = run; g_woff[i] = run;
        run += g_cnt[i];
    }
    if (t == 0) g_off[n] = eN;
}
__global__ void k_scatter(const int* __restrict__ src, const int* __restrict__ dst, int eN) {
    int i = blockIdx.x * blockDim.x + threadIdx.x;
    if (i >= eN) return;
    int pos = atomicAdd(&g_woff[dst[i]], 1);
    g_csr_src[pos] = src[i];
}

// ========== W split: W -> W^T bf16 hi/lo, all 3 layers in one launch ========
__global__ void k_wsplit(const float* __restrict__ W0, const float* __restrict__ W1,
                         const float* __restrict__ W2) {
    __shared__ float t[32][33];
    int L = blockIdx.z;
    const float* W = (L == 0) ? W0 : (L == 1) ? W1 : W2;
    int bx = blockIdx.x, by = blockIdx.y;
    int txx = threadIdx.x, tyy = threadIdx.y;
    t[tyy][txx] = W[(by * 32 + tyy) * D + bx * 32 + txx];
    __syncthreads();
    int n2 = bx * 32 + tyy, k2 = by * 32 + txx;
    float v = t[txx][tyy];
    __nv_bfloat16 hi = __float2bfloat16_rn(v);
    float lo = v - __bfloat162float(hi);
    g_wh[L][n2 * D + k2] = hi;
    g_wl[L][n2 * D + k2] = __float2bfloat16_rn(lo);
}

// ================= mma.sync bf16-split GEMM =================================
__device__ __forceinline__ void mma16816(float* c, uint32_t a0, uint32_t a1,
                                         uint32_t a2, uint32_t a3,
                                         uint32_t b0, uint32_t b1) {
    asm volatile(
        "mma.sync.aligned.m16n8k16.row.col.f32.bf16.bf16.f32 "
        "{%0,%1,%2,%3}, {%4,%5,%6,%7}, {%8,%9}, {%0,%1,%2,%3};"
        : "+f"(c[0]), "+f"(c[1]), "+f"(c[2]), "+f"(c[3])
        : "r"(a0), "r"(a1), "r"(a2), "r"(a3), "r"(b0), "r"(b1));
}
__device__ __forceinline__ uint32_t pack_bf2(float x, float y) {
    __nv_bfloat162 p = __float22bfloat162_rn(make_float2(x, y));
    return *(uint32_t*)&p;
}

#define SMS 136   // padded k-stride (bf16 elems): conflict-free fragment LDS

// z = x@W with fused el/er. CTA: 128 rows x 128 cols, 512 threads, 16 warps.
// Warp (wrow = wid&7, chalf = wid>>3): rows [wrow*16,+16), cols [chalf*64,+64).
__global__ __launch_bounds__(512) void k_gemm_mma(const float* __restrict__ xin,
                                                  int L,
                                                  const float* __restrict__ al,
                                                  const float* __restrict__ ar,
                                                  int n) {
    extern __shared__ char smem[];
    __nv_bfloat16* sA0 = (__nv_bfloat16*)smem;          // x hi [128][SMS]
    __nv_bfloat16* sA1 = sA0 + 128 * SMS;               // x lo
    __nv_bfloat16* sB0 = sA1 + 128 * SMS;               // W^T hi
    __nv_bfloat16* sB1 = sB0 + 128 * SMS;               // W^T lo
    float* sal = (float*)(sB1 + 128 * SMS);
    float* sar = sal + 128;
    float* pel = sar + 128;   // [2][128] col-half partial el
    float* per = pel + 256;   // [2][128] col-half partial er

    const float* x = xin ? xin : g_h;
    int tx = threadIdx.x;
    int wid = tx >> 5, lane = tx & 31;
    int row0 = blockIdx.x * 128;

    if (tx < 128) { sal[tx] = al[tx]; sar[tx] = ar[tx]; }

    // ---- fill B: 512 threads, each copies half a row of one split ----
    {
        const __nv_bfloat16* wsrc = (tx < 256) ? g_wh[L] : g_wl[L];
        __nv_bfloat16* bd = (tx < 256) ? sB0 : sB1;
        int r = (tx >> 1) & 127;
        int half = tx & 1;
        const uint4* sv = (const uint4*)(wsrc + r * D + half * 64);
        uint4* dv = (uint4*)(bd + r * SMS + half * 64);
#pragma unroll
        for (int i = 0; i < 8; i++) dv[i] = sv[i];
    }
    // ---- fill A: fp32 -> bf16 hi/lo, 4 threads per row ----
    {
        int row = tx >> 2, q4 = tx & 3;
        int grow = row0 + row;
        const float4* xr = (const float4*)&x[(size_t)grow * D + q4 * 32];
#pragma unroll
        for (int j = 0; j < 8; j++) {
            float4 v = (grow < n) ? xr[j] : make_float4(0.f, 0.f, 0.f, 0.f);
            __nv_bfloat16 h0 = __float2bfloat16_rn(v.x);
            __nv_bfloat16 h1 = __float2bfloat16_rn(v.y);
            __nv_bfloat16 h2 = __float2bfloat16_rn(v.z);
            __nv_bfloat16 h3 = __float2bfloat16_rn(v.w);
            uint32_t hp0, hp1;
            { __nv_bfloat162 p = make_bfloat162(h0, h1); hp0 = *(uint32_t*)&p; }
            { __nv_bfloat162 p = make_bfloat162(h2, h3); hp1 = *(uint32_t*)&p; }
            uint32_t lp0 = pack_bf2(v.x - __bfloat162float(h0),
                                    v.y - __bfloat162float(h1));
            uint32_t lp1 = pack_bf2(v.z - __bfloat162float(h2),
                                    v.w - __bfloat162float(h3));
            int ko = q4 * 32 + j * 4;
            *(uint2*)&sA0[row * SMS + ko] = make_uint2(hp0, hp1);
            *(uint2*)&sA1[row * SMS + ko] = make_uint2(lp0, lp1);
        }
    }
    __syncthreads();

    // ---- compute ----
    int g = lane >> 2, q = lane & 3;
    int wrow = wid & 7, chalf = wid >> 3;
    int ra = wrow * 16 + g;
    float acc[8][4];
#pragma unroll
    for (int nt = 0; nt < 8; nt++)
#pragma unroll
        for (int p = 0; p < 4; p++) acc[nt][p] = 0.f;

#pragma unroll
    for (int kc = 0; kc < 8; kc++) {
        int ka = kc * 16 + q * 2;
        uint32_t ah0 = *(const uint32_t*)&sA0[ra * SMS + ka];
        uint32_t ah1 = *(const uint32_t*)&sA0[(ra + 8) * SMS + ka];
        uint32_t ah2 = *(const uint32_t*)&sA0[ra * SMS + ka + 8];
        uint32_t ah3 = *(const uint32_t*)&sA0[(ra + 8) * SMS + ka + 8];
        uint32_t av0 = *(const uint32_t*)&sA1[ra * SMS + ka];
        uint32_t av1 = *(const uint32_t*)&sA1[(ra + 8) * SMS + ka];
        uint32_t av2 = *(const uint32_t*)&sA1[ra * SMS + ka + 8];
        uint32_t av3 = *(const uint32_t*)&sA1[(ra + 8) * SMS + ka + 8];
#pragma unroll
        for (int nt = 0; nt < 8; nt++) {
            int nb = chalf * 64 + nt * 8 + g;
            uint32_t bh0 = *(const uint32_t*)&sB0[nb * SMS + ka];
            uint32_t bh1 = *(const uint32_t*)&sB0[nb * SMS + ka + 8];
            uint32_t bl0 = *(const uint32_t*)&sB1[nb * SMS + ka];
            uint32_t bl1 = *(const uint32_t*)&sB1[nb * SMS + ka + 8];
            mma16816(acc[nt], ah0, ah1, ah2, ah3, bh0, bh1);   // hi*hi
            mma16816(acc[nt], ah0, ah1, ah2, ah3, bl0, bl1);   // hi*lo
            mma16816(acc[nt], av0, av1, av2, av3, bh0, bh1);   // lo*hi
        }
    }

    // ---- epilogue: z fp16 stores + fused el/er (exact fp32) ----
    int r1 = row0 + ra, r2 = r1 + 8;
    float el1 = 0.f, er1 = 0.f, el2 = 0.f, er2 = 0.f;
#pragma unroll
    for (int nt = 0; nt < 8; nt++) {
        int c0 = chalf * 64 + nt * 8 + q * 2;
        float a0v = sal[c0], a1v = sal[c0 + 1];
        float r0v = sar[c0], r1v = sar[c0 + 1];
        el1 += acc[nt][0] * a0v + acc[nt][1] * a1v;
        er1 += acc[nt][0] * r0v + acc[nt][1] * r1v;
        el2 += acc[nt][2] * a0v + acc[nt][3] * a1v;
        er2 += acc[nt][2] * r0v + acc[nt][3] * r1v;
        if (r1 < n)
            *(__half2*)&g_z16[(size_t)r1 * D + c0] =
                __floats2half2_rn(acc[nt][0], acc[nt][1]);
        if (r2 < n)
            *(__half2*)&g_z16[(size_t)r2 * D + c0] =
                __floats2half2_rn(acc[nt][2], acc[nt][3]);
    }
#pragma unroll
    for (int o = 1; o <= 2; o <<= 1) {
        el1 += __shfl_xor_sync(0xffffffffu, el1, o);
        er1 += __shfl_xor_sync(0xffffffffu, er1, o);
        el2 += __shfl_xor_sync(0xffffffffu, el2, o);
        er2 += __shfl_xor_sync(0xffffffffu, er2, o);
    }
    if (q == 0) {
        pel[chalf * 128 + ra]     = el1;
        pel[chalf * 128 + ra + 8] = el2;
        per[chalf * 128 + ra]     = er1;
        per[chalf * 128 + ra + 8] = er2;
    }
    __syncthreads();
    if (tx < 128) {
        int r = row0 + tx;
        if (r < n) {
            g_el[r] = pel[tx] + pel[128 + tx];
            g_er[r] = per[tx] + per[128 + tx];
        }
    }
}

#define GEMM_SMEM (4 * 128 * SMS * 2 + 2 * 128 * 4 + 4 * 128 * 4)

// ---- fp16 fma from an 8-byte row chunk (4 halves) ----
__device__ __forceinline__ void fma_h4(float4& a, const uint2& raw, float al) {
    float2 f0 = __half22float2(*(const __half2*)&raw.x);
    float2 f1 = __half22float2(*(const __half2*)&raw.y);
    a.x = fmaf(al, f0.x, a.x); a.y = fmaf(al, f0.y, a.y);
    a.z = fmaf(al, f1.x, a.z); a.w = fmaf(al, f1.y, a.w);
}

// ===== Fused per-dst softmax + aggregate + bias + ReLU =====================
// ONE warp per dst: full-warp softmax (no max pass — exp is range-safe here),
// column-split gather (lanes 0-15 cols [0,64), lanes 16-31 cols [64,128)) so
// both half-warps iterate identical deg: zero divergence.
__global__ __launch_bounds__(256) void k_edge(const float* __restrict__ b,
                                              float* __restrict__ hout, int n) {
    __shared__ float2 spair[8][64];
    int tx = threadIdx.x;
    int w = tx >> 5, lane = tx & 31;
    int d = blockIdx.x * 8 + w;
    if (d >= n) return;
    int lane16 = lane & 15;
    int half = lane >> 4;
    int colo = half * 64 + lane16 * 4;
    int r0 = g_off[d];
    int deg = g_off[d + 1] - r0;
    float4 accA = make_float4(0.f, 0.f, 0.f, 0.f);
    float4 accB = make_float4(0.f, 0.f, 0.f, 0.f);
    float inv = 0.f;
    const unsigned FM = 0xffffffffu;

    if (deg > 0 && deg <= 64) {
        float erd = g_er[d];
        float ssum = 0.f;
#pragma unroll
        for (int c = 0; c < 2; c++) {
            int idx = c * 32 + lane;
            if (idx < deg) {
                int s = g_csr_src[r0 + idx];
                float e = g_el[s] + erd;
                e = e > 0.f ? e : 0.2f * e;
                float ex = __expf(e);
                ssum += ex;
                spair[w][idx] = make_float2(__int_as_float(s), ex);
            }
        }
#pragma unroll
        for (int o = 16; o > 0; o >>= 1)
            ssum += __shfl_xor_sync(FM, ssum, o);
        inv = 1.0f / ssum;
        __syncwarp(FM);
        // gather: broadcast LDS.128 (2 pairs), LDG.64 per lane = full 256B row/warp
        int j = 0;
        for (; j + 1 < deg; j += 2) {
            float4 pp = *(const float4*)&spair[w][j];
            int s0 = __float_as_int(pp.x);
            int s1 = __float_as_int(pp.z);
            uint2 r0v = *(const uint2*)&g_z16[(size_t)s0 * D + colo];
            uint2 r1v = *(const uint2*)&g_z16[(size_t)s1 * D + colo];
            fma_h4(accA, r0v, pp.y);
            fma_h4(accB, r1v, pp.w);
        }
        if (j < deg) {
            float2 p = spair[w][j];
            uint2 rv = *(const uint2*)&g_z16[(size_t)__float_as_int(p.x) * D + colo];
            fma_h4(accA, rv, p.y);
        }
    } else if (deg > 64) {
        // fallback: via g_e (rare high-degree nodes), full warp
        float erd = g_er[d];
        float ssum = 0.f;
        for (int i = lane; i < deg; i += 32) {
            int s = g_csr_src[r0 + i];
            float e = g_el[s] + erd;
            e = e > 0.f ? e : 0.2f * e;
            float ex = __expf(e);
            g_e[r0 + i] = ex;
            ssum += ex;
        }
#pragma unroll
        for (int o = 16; o > 0; o >>= 1)
            ssum += __shfl_xor_sync(FM, ssum, o);
        inv = 1.0f / ssum;
        __syncwarp(FM);
        for (int j = 0; j < deg; j++) {
            int s = g_csr_src[r0 + j];          // broadcast load
            float a = g_e[r0 + j];              // broadcast load
            uint2 rv = *(const uint2*)&g_z16[(size_t)s * D + colo];
            fma_h4(accA, rv, a);
        }
    }
    float4 bv = *(const float4*)&b[colo];
    float4 o;
    o.x = fmaxf(fmaf(accA.x + accB.x, inv, bv.x), 0.f);
    o.y = fmaxf(fmaf(accA.y + accB.y, inv, bv.y), 0.f);
    o.z = fmaxf(fmaf(accA.z + accB.z, inv, bv.z), 0.f);
    o.w = fmaxf(fmaf(accA.w + accB.w, inv, bv.w), 0.f);
    float* out = hout ? hout : g_h;
    *(float4*)&out[(size_t)d * D + colo] = o;
}

// -------- launch --------
extern "C" void kernel_launch(void* const* d_in, const int* in_sizes, int n_in,
                              void* d_out, int out_size) {
    const float* f   = (const float*)d_in[0];
    const int*   src = (const int*)d_in[1];
    const int*   dst = (const int*)d_in[2];
    const float* W[3]  = { (const float*)d_in[3], (const float*)d_in[7],  (const float*)d_in[11] };
    const float* al[3] = { (const float*)d_in[4], (const float*)d_in[8],  (const float*)d_in[12] };
    const float* ar[3] = { (const float*)d_in[5], (const float*)d_in[9],  (const float*)d_in[13] };
    const float* bb[3] = { (const float*)d_in[6], (const float*)d_in[10], (const float*)d_in[14] };

    int n  = in_sizes[0] / D;
    int eN = in_sizes[1];
    float* out = (float*)d_out;

    static cudaStream_t s2 = nullptr;
    static cudaEvent_t evFork = nullptr, evJoin = nullptr;
    static void* cntPtr = nullptr;
    if (!s2) {
        cudaStreamCreateWithFlags(&s2, cudaStreamNonBlocking);
        cudaEventCreateWithFlags(&evFork, cudaEventDisableTiming);
        cudaEventCreateWithFlags(&evJoin, cudaEventDisableTiming);
        cudaGetSymbolAddress(&cntPtr, g_cnt);
        cudaFuncSetAttribute(k_gemm_mma, cudaFuncAttributeMaxDynamicSharedMemorySize,
                             GEMM_SMEM);
    }

    // Fork: CSR build on s2, overlapped with wsplit + layer-1 GEMM.
    cudaEventRecord(evFork, 0);
    cudaStreamWaitEvent(s2, evFork, 0);
    cudaMemsetAsync(cntPtr, 0, (size_t)n * sizeof(int), s2);
    k_hist   <<<(eN + 255) / 256, 256, 0, s2>>>(dst, eN);
    k_scan   <<<1, 1024, 0, s2>>>(n, eN);
    k_scatter<<<(eN + 255) / 256, 256, 0, s2>>>(src, dst, eN);
    cudaEventRecord(evJoin, s2);

    // W hi/lo splits (all layers, one launch) + layer-1 GEMM on main stream
    k_wsplit<<<dim3(4, 4, 3), dim3(32, 32)>>>(W[0], W[1], W[2]);

    int gemmGrid = (n + 127) / 128;
    k_gemm_mma<<<gemmGrid, 512, GEMM_SMEM>>>(f, 0, al[0], ar[0], n);

    cudaStreamWaitEvent(0, evJoin, 0);

    int edgeGrid = (n + 7) / 8;
    k_edge<<<edgeGrid, 256>>>(bb[0], nullptr, n);

    for (int L = 1; L < 3; L++) {
        float* hout = (L == 2) ? out : nullptr;
        k_gemm_mma<<<gemmGrid, 512, GEMM_SMEM>>>(nullptr, L, al[L], ar[L], n);
        k_edge<<<edgeGrid, 256>>>(bb[L], hout, n);
    }
}

// round 17
// speedup vs baseline: 1.0314x; 1.0314x over previous
#include <cuda_runtime.h>
#include <cuda_bf16.h>
#include <cuda_fp16.h>
#include <math_constants.h>
#include <cstdint>

#define D 128
#define MAXN 50000
#define MAXE 800000

// -------- scratch (device globals: allocation-free contract) --------
__device__ __half g_z16[MAXN * D];    // projected features (fp16, gather path)
__device__ float g_h[MAXN * D];       // layer output -> next layer input
__device__ float g_el[MAXN];
__device__ float g_er[MAXN];
__device__ float g_e[MAXE];           // per-edge scratch (fallback path only)
__device__ int   g_cnt[MAXN];
__device__ int   g_off[MAXN + 1];
__device__ int   g_woff[MAXN];
__device__ int   g_csr_src[MAXE];
__device__ __nv_bfloat16 g_wh[3][D * D];   // W^T hi split, [n][k] K-major
__device__ __nv_bfloat16 g_wl[3][D * D];   // W^T lo split

// ================= CSR build ================================================

__global__ void k_hist(const int* __restrict__ dst, int eN) {
    int i = blockIdx.x * blockDim.x + threadIdx.x;
    if (i < eN) atomicAdd(&g_cnt[dst[i]], 1);
}
__global__ __launch_bounds__(1024) void k_scan(int n, int eN) {
    __shared__ int part[1024];
    int t = threadIdx.x;
    int chunk = (n + 1023) / 1024;
    int lo = t * chunk;
    int hi = lo + chunk; if (hi > n) hi = n; if (lo > n) lo = n;
    int s = 0;
    for (int i = lo; i < hi; i++) s += g_cnt[i];
    part[t] = s;
    __syncthreads();
    for (int off = 1; off < 1024; off <<= 1) {
        int v = (t >= off) ? part[t - off] : 0;
        __syncthreads();
        part[t] += v;
        __syncthreads();
    }
    int run = (t == 0) ? 0 : part[t - 1];
    for (int i = lo; i < hi; i++) {
        g_off[i] = run; g_woff[i] = run;
        run += g_cnt[i];
    }
    if (t == 0) g_off[n] = eN;
}
__global__ void k_scatter(const int* __restrict__ src, const int* __restrict__ dst, int eN) {
    int i = blockIdx.x * blockDim.x + threadIdx.x;
    if (i >= eN) return;
    int pos = atomicAdd(&g_woff[dst[i]], 1);
    g_csr_src[pos] = src[i];
}

// ========== W split: W -> W^T bf16 hi/lo, all 3 layers in one launch ========
__global__ void k_wsplit(const float* __restrict__ W0, const float* __restrict__ W1,
                         const float* __restrict__ W2) {
    __shared__ float t[32][33];
    int L = blockIdx.z;
    const float* W = (L == 0) ? W0 : (L == 1) ? W1 : W2;
    int bx = blockIdx.x, by = blockIdx.y;
    int txx = threadIdx.x, tyy = threadIdx.y;
    t[tyy][txx] = W[(by * 32 + tyy) * D + bx * 32 + txx];
    __syncthreads();
    int n2 = bx * 32 + tyy, k2 = by * 32 + txx;
    float v = t[txx][tyy];
    __nv_bfloat16 hi = __float2bfloat16_rn(v);
    float lo = v - __bfloat162float(hi);
    g_wh[L][n2 * D + k2] = hi;
    g_wl[L][n2 * D + k2] = __float2bfloat16_rn(lo);
}

// ================= mma.sync bf16-split GEMM =================================
__device__ __forceinline__ void mma16816(float* c, uint32_t a0, uint32_t a1,
                                         uint32_t a2, uint32_t a3,
                                         uint32_t b0, uint32_t b1) {
    asm volatile(
        "mma.sync.aligned.m16n8k16.row.col.f32.bf16.bf16.f32 "
        "{%0,%1,%2,%3}, {%4,%5,%6,%7}, {%8,%9}, {%0,%1,%2,%3};"
        : "+f"(c[0]), "+f"(c[1]), "+f"(c[2]), "+f"(c[3])
        : "r"(a0), "r"(a1), "r"(a2), "r"(a3), "r"(b0), "r"(b1));
}
__device__ __forceinline__ uint32_t pack_bf2(float x, float y) {
    __nv_bfloat162 p = __float22bfloat162_rn(make_float2(x, y));
    return *(uint32_t*)&p;
}

#define SMS 136   // padded k-stride (bf16 elems): conflict-free fragment LDS

// z = x@W with fused el/er. CTA: 128 rows x 128 cols, 512 threads, 16 warps.
// Warp (wrow = wid&7, chalf = wid>>3): rows [wrow*16,+16), cols [chalf*64,+64).
__global__ __launch_bounds__(512) void k_gemm_mma(const float* __restrict__ xin,
                                                  int L,
                                                  const float* __restrict__ al,
                                                  const float* __restrict__ ar,
                                                  int n) {
    extern __shared__ char smem[];
    __nv_bfloat16* sA0 = (__nv_bfloat16*)smem;          // x hi [128][SMS]
    __nv_bfloat16* sA1 = sA0 + 128 * SMS;               // x lo
    __nv_bfloat16* sB0 = sA1 + 128 * SMS;               // W^T hi
    __nv_bfloat16* sB1 = sB0 + 128 * SMS;               // W^T lo
    float* sal = (float*)(sB1 + 128 * SMS);
    float* sar = sal + 128;
    float* pel = sar + 128;   // [2][128] col-half partial el
    float* per = pel + 256;   // [2][128] col-half partial er

    const float* x = xin ? xin : g_h;
    int tx = threadIdx.x;
    int wid = tx >> 5, lane = tx & 31;
    int row0 = blockIdx.x * 128;

    if (tx < 128) { sal[tx] = al[tx]; sar[tx] = ar[tx]; }

    // ---- fill B: 512 threads, each copies half a row of one split ----
    {
        const __nv_bfloat16* wsrc = (tx < 256) ? g_wh[L] : g_wl[L];
        __nv_bfloat16* bd = (tx < 256) ? sB0 : sB1;
        int r = (tx >> 1) & 127;
        int half = tx & 1;
        const uint4* sv = (const uint4*)(wsrc + r * D + half * 64);
        uint4* dv = (uint4*)(bd + r * SMS + half * 64);
#pragma unroll
        for (int i = 0; i < 8; i++) dv[i] = sv[i];
    }
    // ---- fill A: fp32 -> bf16 hi/lo, 4 threads per row ----
    {
        int row = tx >> 2, q4 = tx & 3;
        int grow = row0 + row;
        const float4* xr = (const float4*)&x[(size_t)grow * D + q4 * 32];
#pragma unroll
        for (int j = 0; j < 8; j++) {
            float4 v = (grow < n) ? xr[j] : make_float4(0.f, 0.f, 0.f, 0.f);
            __nv_bfloat16 h0 = __float2bfloat16_rn(v.x);
            __nv_bfloat16 h1 = __float2bfloat16_rn(v.y);
            __nv_bfloat16 h2 = __float2bfloat16_rn(v.z);
            __nv_bfloat16 h3 = __float2bfloat16_rn(v.w);
            uint32_t hp0, hp1;
            { __nv_bfloat162 p = make_bfloat162(h0, h1); hp0 = *(uint32_t*)&p; }
            { __nv_bfloat162 p = make_bfloat162(h2, h3); hp1 = *(uint32_t*)&p; }
            uint32_t lp0 = pack_bf2(v.x - __bfloat162float(h0),
                                    v.y - __bfloat162float(h1));
            uint32_t lp1 = pack_bf2(v.z - __bfloat162float(h2),
                                    v.w - __bfloat162float(h3));
            int ko = q4 * 32 + j * 4;
            *(uint2*)&sA0[row * SMS + ko] = make_uint2(hp0, hp1);
            *(uint2*)&sA1[row * SMS + ko] = make_uint2(lp0, lp1);
        }
    }
    __syncthreads();

    // ---- compute ----
    int g = lane >> 2, q = lane & 3;
    int wrow = wid & 7, chalf = wid >> 3;
    int ra = wrow * 16 + g;
    float acc[8][4];
#pragma unroll
    for (int nt = 0; nt < 8; nt++)
#pragma unroll
        for (int p = 0; p < 4; p++) acc[nt][p] = 0.f;

#pragma unroll
    for (int kc = 0; kc < 8; kc++) {
        int ka = kc * 16 + q * 2;
        uint32_t ah0 = *(const uint32_t*)&sA0[ra * SMS + ka];
        uint32_t ah1 = *(const uint32_t*)&sA0[(ra + 8) * SMS + ka];
        uint32_t ah2 = *(const uint32_t*)&sA0[ra * SMS + ka + 8];
        uint32_t ah3 = *(const uint32_t*)&sA0[(ra + 8) * SMS + ka + 8];
        uint32_t av0 = *(const uint32_t*)&sA1[ra * SMS + ka];
        uint32_t av1 = *(const uint32_t*)&sA1[(ra + 8) * SMS + ka];
        uint32_t av2 = *(const uint32_t*)&sA1[ra * SMS + ka + 8];
        uint32_t av3 = *(const uint32_t*)&sA1[(ra + 8) * SMS + ka + 8];
#pragma unroll
        for (int nt = 0; nt < 8; nt++) {
            int nb = chalf * 64 + nt * 8 + g;
            uint32_t bh0 = *(const uint32_t*)&sB0[nb * SMS + ka];
            uint32_t bh1 = *(const uint32_t*)&sB0[nb * SMS + ka + 8];
            uint32_t bl0 = *(const uint32_t*)&sB1[nb * SMS + ka];
            uint32_t bl1 = *(const uint32_t*)&sB1[nb * SMS + ka + 8];
            mma16816(acc[nt], ah0, ah1, ah2, ah3, bh0, bh1);   // hi*hi
            mma16816(acc[nt], ah0, ah1, ah2, ah3, bl0, bl1);   // hi*lo
            mma16816(acc[nt], av0, av1, av2, av3, bh0, bh1);   // lo*hi
        }
    }

    // ---- epilogue: z fp16 stores + fused el/er (exact fp32) ----
    int r1 = row0 + ra, r2 = r1 + 8;
    float el1 = 0.f, er1 = 0.f, el2 = 0.f, er2 = 0.f;
#pragma unroll
    for (int nt = 0; nt < 8; nt++) {
        int c0 = chalf * 64 + nt * 8 + q * 2;
        float a0v = sal[c0], a1v = sal[c0 + 1];
        float r0v = sar[c0], r1v = sar[c0 + 1];
        el1 += acc[nt][0] * a0v + acc[nt][1] * a1v;
        er1 += acc[nt][0] * r0v + acc[nt][1] * r1v;
        el2 += acc[nt][2] * a0v + acc[nt][3] * a1v;
        er2 += acc[nt][2] * r0v + acc[nt][3] * r1v;
        if (r1 < n)
            *(__half2*)&g_z16[(size_t)r1 * D + c0] =
                __floats2half2_rn(acc[nt][0], acc[nt][1]);
        if (r2 < n)
            *(__half2*)&g_z16[(size_t)r2 * D + c0] =
                __floats2half2_rn(acc[nt][2], acc[nt][3]);
    }
#pragma unroll
    for (int o = 1; o <= 2; o <<= 1) {
        el1 += __shfl_xor_sync(0xffffffffu, el1, o);
        er1 += __shfl_xor_sync(0xffffffffu, er1, o);
        el2 += __shfl_xor_sync(0xffffffffu, el2, o);
        er2 += __shfl_xor_sync(0xffffffffu, er2, o);
    }
    if (q == 0) {
        pel[chalf * 128 + ra]     = el1;
        pel[chalf * 128 + ra + 8] = el2;
        per[chalf * 128 + ra]     = er1;
        per[chalf * 128 + ra + 8] = er2;
    }
    __syncthreads();
    if (tx < 128) {
        int r = row0 + tx;
        if (r < n) {
            g_el[r] = pel[tx] + pel[128 + tx];
            g_er[r] = per[tx] + per[128 + tx];
        }
    }
}

#define GEMM_SMEM (4 * 128 * SMS * 2 + 2 * 128 * 4 + 4 * 128 * 4)

// ---- fp16 fma from preloaded 16B row chunk ----
__device__ __forceinline__ void fma_raw(float4& a0, float4& a1,
                                        const uint4& raw, float a) {
    float2 f0 = __half22float2(*(const __half2*)&raw.x);
    float2 f1 = __half22float2(*(const __half2*)&raw.y);
    float2 f2 = __half22float2(*(const __half2*)&raw.z);
    float2 f3 = __half22float2(*(const __half2*)&raw.w);
    a0.x = fmaf(a, f0.x, a0.x); a0.y = fmaf(a, f0.y, a0.y);
    a0.z = fmaf(a, f1.x, a0.z); a0.w = fmaf(a, f1.y, a0.w);
    a1.x = fmaf(a, f2.x, a1.x); a1.y = fmaf(a, f2.y, a1.y);
    a1.z = fmaf(a, f3.x, a1.z); a1.w = fmaf(a, f3.y, a1.w);
}
__device__ __forceinline__ const uint4* zrow(int srow, int lane16) {
    return (const uint4*)&g_z16[(size_t)srow * D + lane16 * 8];
}

// ===== Fused per-dst softmax + aggregate + bias + ReLU =====================
// TWO dsts per warp (16-lane groups; best measured shape). No-max softmax
// (shift-invariant, range-safe). Gather: LDS.128 per 2 (src,ex) pairs,
// LDG.128 per lane (full 256B row per 16-lane group), 2 acc chains.
__global__ __launch_bounds__(256) void k_edge(const float* __restrict__ b,
                                              float* __restrict__ hout, int n) {
    __shared__ float2 spair[16][64];
    int tx = threadIdx.x;
    int d = (blockIdx.x * blockDim.x + tx) >> 4;
    int lane16 = tx & 15;
    int gi = tx >> 4;
    if (d >= n) return;
    int r0 = g_off[d];
    int deg = g_off[d + 1] - r0;
    float4 accA0 = make_float4(0.f, 0.f, 0.f, 0.f);
    float4 accA1 = make_float4(0.f, 0.f, 0.f, 0.f);
    float4 accB0 = make_float4(0.f, 0.f, 0.f, 0.f);
    float4 accB1 = make_float4(0.f, 0.f, 0.f, 0.f);
    float inv = 0.f;
    const unsigned FM = 0xffffffffu;

    if (deg > 0 && deg <= 64) {
        float erd = g_er[d];
        float ssum = 0.f;
#pragma unroll
        for (int c = 0; c < 4; c++) {
            int idx = c * 16 + lane16;
            if (idx < deg) {
                int s = g_csr_src[r0 + idx];
                float e = g_el[s] + erd;
                e = e > 0.f ? e : 0.2f * e;
                float ex = __expf(e);
                ssum += ex;
                spair[gi][idx] = make_float2(__int_as_float(s), ex);
            }
        }
#pragma unroll
        for (int o = 8; o > 0; o >>= 1)
            ssum += __shfl_xor_sync(FM, ssum, o, 16);
        inv = 1.0f / ssum;
        __syncwarp(__activemask());
        // gather: one LDS.128 per 2 edges, 2 independent LDG.128 + acc chains
        int j = 0;
        for (; j + 1 < deg; j += 2) {
            float4 pp = *(const float4*)&spair[gi][j];
            uint4 r0v = *zrow(__float_as_int(pp.x), lane16);
            uint4 r1v = *zrow(__float_as_int(pp.z), lane16);
            fma_raw(accA0, accA1, r0v, pp.y);
            fma_raw(accB0, accB1, r1v, pp.w);
        }
        if (j < deg) {
            float2 p0 = spair[gi][j];
            uint4 r0v = *zrow(__float_as_int(p0.x), lane16);
            fma_raw(accA0, accA1, r0v, p0.y);
        }
    } else if (deg > 64) {
        // fallback: via g_e (rare high-degree nodes), 16 lanes, no-max
        float erd = g_er[d];
        float ssum = 0.f;
        for (int i = lane16; i < deg; i += 16) {
            int s = g_csr_src[r0 + i];
            float e = g_el[s] + erd;
            e = e > 0.f ? e : 0.2f * e;
            float ex = __expf(e);
            g_e[r0 + i] = ex;
            ssum += ex;
        }
#pragma unroll
        for (int o = 8; o > 0; o >>= 1)
            ssum += __shfl_xor_sync(FM, ssum, o, 16);
        inv = 1.0f / ssum;
        for (int c = 0; c < deg; c += 16) {
            int idx = c + lane16;
            int   sl = 0; float exl = 0.f;
            if (idx < deg) { sl = g_csr_src[r0 + idx]; exl = g_e[r0 + idx]; }
            int lim = deg - c; if (lim > 16) lim = 16;
            for (int j = 0; j < lim; j++) {
                int   sj = __shfl_sync(FM, sl, j, 16);
                float a  = __shfl_sync(FM, exl, j, 16);
                uint4 rv = *zrow(sj, lane16);
                fma_raw(accA0, accA1, rv, a);
            }
        }
    }
    float4 b0 = *(const float4*)&b[lane16 * 8];
    float4 b1 = *(const float4*)&b[lane16 * 8 + 4];
    float4 o0, o1;
    o0.x = fmaxf(fmaf(accA0.x + accB0.x, inv, b0.x), 0.f);
    o0.y = fmaxf(fmaf(accA0.y + accB0.y, inv, b0.y), 0.f);
    o0.z = fmaxf(fmaf(accA0.z + accB0.z, inv, b0.z), 0.f);
    o0.w = fmaxf(fmaf(accA0.w + accB0.w, inv, b0.w), 0.f);
    o1.x = fmaxf(fmaf(accA1.x + accB1.x, inv, b1.x), 0.f);
    o1.y = fmaxf(fmaf(accA1.y + accB1.y, inv, b1.y), 0.f);
    o1.z = fmaxf(fmaf(accA1.z + accB1.z, inv, b1.z), 0.f);
    o1.w = fmaxf(fmaf(accA1.w + accB1.w, inv, b1.w), 0.f);
    float* out = hout ? hout : g_h;
    *(float4*)&out[(size_t)d * D + lane16 * 8]     = o0;
    *(float4*)&out[(size_t)d * D + lane16 * 8 + 4] = o1;
}

// -------- launch --------
extern "C" void kernel_launch(void* const* d_in, const int* in_sizes, int n_in,
                              void* d_out, int out_size) {
    const float* f   = (const float*)d_in[0];
    const int*   src = (const int*)d_in[1];
    const int*   dst = (const int*)d_in[2];
    const float* W[3]  = { (const float*)d_in[3], (const float*)d_in[7],  (const float*)d_in[11] };
    const float* al[3] = { (const float*)d_in[4], (const float*)d_in[8],  (const float*)d_in[12] };
    const float* ar[3] = { (const float*)d_in[5], (const float*)d_in[9],  (const float*)d_in[13] };
    const float* bb[3] = { (const float*)d_in[6], (const float*)d_in[10], (const float*)d_in[14] };

    int n  = in_sizes[0] / D;
    int eN = in_sizes[1];
    float* out = (float*)d_out;

    static cudaStream_t s2 = nullptr;
    static cudaEvent_t evFork = nullptr, evJoin = nullptr;
    static void* cntPtr = nullptr;
    if (!s2) {
        cudaStreamCreateWithFlags(&s2, cudaStreamNonBlocking);
        cudaEventCreateWithFlags(&evFork, cudaEventDisableTiming);
        cudaEventCreateWithFlags(&evJoin, cudaEventDisableTiming);
        cudaGetSymbolAddress(&cntPtr, g_cnt);
        cudaFuncSetAttribute(k_gemm_mma, cudaFuncAttributeMaxDynamicSharedMemorySize,
                             GEMM_SMEM);
    }

    // Fork: CSR build on s2, overlapped with wsplit + layer-1 GEMM.
    cudaEventRecord(evFork, 0);
    cudaStreamWaitEvent(s2, evFork, 0);
    cudaMemsetAsync(cntPtr, 0, (size_t)n * sizeof(int), s2);
    k_hist   <<<(eN + 255) / 256, 256, 0, s2>>>(dst, eN);
    k_scan   <<<1, 1024, 0, s2>>>(n, eN);
    k_scatter<<<(eN + 255) / 256, 256, 0, s2>>>(src, dst, eN);
    cudaEventRecord(evJoin, s2);

    // W hi/lo splits (all layers, one launch) + layer-1 GEMM on main stream
    k_wsplit<<<dim3(4, 4, 3), dim3(32, 32)>>>(W[0], W[1], W[2]);

    int gemmGrid = (n + 127) / 128;
    k_gemm_mma<<<gemmGrid, 512, GEMM_SMEM>>>(f, 0, al[0], ar[0], n);

    cudaStreamWaitEvent(0, evJoin, 0);

    int edgeGrid = (n + 15) / 16;
    k_edge<<<edgeGrid, 256>>>(bb[0], nullptr, n);

    for (int L = 1; L < 3; L++) {
        float* hout = (L == 2) ? out : nullptr;
        k_gemm_mma<<<gemmGrid, 512, GEMM_SMEM>>>(nullptr, L, al[L], ar[L], n);
        k_edge<<<edgeGrid, 256>>>(bb[L], hout, n);
    }
}